// round 6
// baseline (speedup 1.0000x reference)
#include <cuda_runtime.h>
#include <math.h>

// Problem constants (fixed by the reference)
#define NN 6000          // N_USERS + N_ITEMS
#define EE 100000        // edges
#define NREL 2

// ---------------------------------------------------------------------------
// Device scratch (static device globals — no runtime allocation)
// ---------------------------------------------------------------------------
__device__ int   g_cnt[NN];
__device__ int   g_rowptr[NN + 1];
__device__ int   g_cursor[NN];
__device__ int   g_ssrc[EE];        // CSR (by dst): source node per slot
__device__ int   g_stype[EE];       // CSR: edge type per slot

__device__ float g_W0[2 * NN * 32]; // layer-0 relation weights W[r][n][o]
__device__ float g_xa[NN * 512];    // ping buffer
__device__ float g_xb[NN * 512];    // pong buffer
__device__ float g_HR[NN * 192];    // per-layer [x@W0 | x@W1 | x@root]
__device__ float g_Wcat[64 * 192];  // per-layer fused weight [in, 3*out]
__device__ float g_asv[NN];
__device__ float g_adv[NN];
__device__ float g_coef[EE];        // GAT normalized attention per CSR slot
__device__ float g_self[NN];        // GAT self-loop attention
__device__ float g_A[NN * 128];     // x @ w1[0:512]
__device__ float g_B[NN * 128];     // x @ w1[512:1024]

__device__ __forceinline__ float lrelu(float x) { return x > 0.f ? x : 0.2f * x; }

// ---------------------------------------------------------------------------
// CSR build
// ---------------------------------------------------------------------------
__global__ void k_zero_cnt() {
    int i = blockIdx.x * blockDim.x + threadIdx.x;
    if (i < NN) g_cnt[i] = 0;
}

__global__ void k_hist(const int* __restrict__ dst) {
    int e = blockIdx.x * blockDim.x + threadIdx.x;
    if (e < EE) atomicAdd(&g_cnt[dst[e]], 1);
}

__global__ void k_scan() {
    __shared__ int sp[256];
    int tid = threadIdx.x;
    const int CH = (NN + 255) / 256;   // 24
    int base = tid * CH;
    int s = 0;
    for (int i = 0; i < CH; i++) {
        int idx = base + i;
        if (idx < NN) s += g_cnt[idx];
    }
    sp[tid] = s;
    __syncthreads();
    for (int off = 1; off < 256; off <<= 1) {
        int v = 0;
        if (tid >= off) v = sp[tid - off];
        __syncthreads();
        sp[tid] += v;
        __syncthreads();
    }
    int run = sp[tid] - s;  // exclusive prefix for this chunk
    for (int i = 0; i < CH; i++) {
        int idx = base + i;
        if (idx < NN) {
            g_rowptr[idx] = run;
            g_cursor[idx] = run;
            run += g_cnt[idx];
        }
    }
    if (tid == 255) g_rowptr[NN] = sp[255];
}

__global__ void k_scatter(const int* __restrict__ src, const int* __restrict__ dst,
                          const int* __restrict__ et) {
    int e = blockIdx.x * blockDim.x + threadIdx.x;
    if (e < EE) {
        int p = atomicAdd(&g_cursor[dst[e]], 1);
        g_ssrc[p]  = src[e];
        g_stype[p] = et[e];
    }
}

// ---------------------------------------------------------------------------
// Layer 0 (x = I): W0[r] = sum_b comp0[r,b]*basis0[b]  (basis0: [4, NN, 32])
// ---------------------------------------------------------------------------
__global__ void k_w0(const float* __restrict__ basis0, const float* __restrict__ comp0) {
    int i = blockIdx.x * blockDim.x + threadIdx.x;
    if (i >= 2 * NN * 32) return;
    int r   = i / (NN * 32);
    int rem = i - r * (NN * 32);
    int n   = rem >> 5;
    int o   = rem & 31;
    float v = 0.f;
#pragma unroll
    for (int b = 0; b < 4; b++)
        v += comp0[r * 4 + b] * basis0[(b * NN + n) * 32 + o];
    g_W0[i] = v;
}

// out[n] = tanh(root0[n] + rbias0 + sum_r mean_{e->n, type r} W0[r][src_e])
__global__ void k_layer0(const float* __restrict__ root0, const float* __restrict__ rbias0) {
    int warp = (blockIdx.x * blockDim.x + threadIdx.x) >> 5;
    int lane = threadIdx.x & 31;
    if (warp >= NN) return;
    int n = warp;
    int beg = g_rowptr[n], end = g_rowptr[n + 1];
    float a0 = 0.f, a1 = 0.f;
    int c0 = 0, c1 = 0;
    for (int e = beg; e < end; e++) {
        int s = g_ssrc[e];
        int t = g_stype[e];
        float v = g_W0[(t * NN + s) * 32 + lane];
        if (t == 0) { a0 += v; c0++; } else { a1 += v; c1++; }
    }
    float o = root0[n * 32 + lane] + rbias0[lane]
            + a0 / fmaxf((float)c0, 1.f) + a1 / fmaxf((float)c1, 1.f);
    g_xa[n * 32 + lane] = tanhf(o);
}

// ---------------------------------------------------------------------------
// Layers 1..3: Wcat = [W0 | W1 | root]  ([in, 3*out]); HR = x @ Wcat; aggregate
// ---------------------------------------------------------------------------
__global__ void k_wcat(const float* __restrict__ basis, const float* __restrict__ comp,
                       const float* __restrict__ root, int IN, int OUT) {
    int J = 3 * OUT;
    int i = blockIdx.x * blockDim.x + threadIdx.x;
    if (i >= IN * J) return;
    int k = i / J;
    int j = i - k * J;
    float v;
    if (j < 2 * OUT) {
        int r = j / OUT;
        int o = j - r * OUT;
        v = 0.f;
#pragma unroll
        for (int b = 0; b < 4; b++)
            v += comp[r * 4 + b] * basis[(b * IN + k) * OUT + o];
    } else {
        v = root[k * OUT + (j - 2 * OUT)];
    }
    g_Wcat[i] = v;
}

// HR[n, :] = x[n, :] @ Wcat  -- thread computes 4 contiguous columns
__global__ void k_hr(int xsel, int IN, int OUT) {
    const float* x = xsel ? g_xb : g_xa;
    int J = 3 * OUT;
    int cpr = J >> 2;
    int t = blockIdx.x * blockDim.x + threadIdx.x;
    if (t >= NN * cpr) return;
    int n  = t / cpr;
    int c4 = (t - n * cpr) << 2;
    const float* xr = x + n * IN;
    float4 acc = make_float4(0.f, 0.f, 0.f, 0.f);
    for (int k = 0; k < IN; k++) {
        float xv = __ldg(xr + k);
        float4 w = *(const float4*)(g_Wcat + k * J + c4);
        acc.x += xv * w.x; acc.y += xv * w.y; acc.z += xv * w.z; acc.w += xv * w.w;
    }
    *(float4*)(g_HR + n * J + c4) = acc;
}

template <int OUT>
__global__ void k_agg(const float* __restrict__ rbias, int osel) {
    float* xout = osel ? g_xb : g_xa;
    const int J = 3 * OUT;
    const int CPL = OUT / 32;
    int warp = (blockIdx.x * blockDim.x + threadIdx.x) >> 5;
    int lane = threadIdx.x & 31;
    if (warp >= NN) return;
    int n = warp;
    int beg = g_rowptr[n], end = g_rowptr[n + 1];
    float a0[CPL], a1[CPL];
#pragma unroll
    for (int i = 0; i < CPL; i++) { a0[i] = 0.f; a1[i] = 0.f; }
    int c0 = 0, c1 = 0;
    for (int e = beg; e < end; e++) {
        int s = g_ssrc[e];
        int t = g_stype[e];
        const float* hrow = g_HR + s * J + t * OUT;
        if (t == 0) {
            c0++;
#pragma unroll
            for (int i = 0; i < CPL; i++) a0[i] += hrow[lane + i * 32];
        } else {
            c1++;
#pragma unroll
            for (int i = 0; i < CPL; i++) a1[i] += hrow[lane + i * 32];
        }
    }
    float i0 = 1.f / fmaxf((float)c0, 1.f);
    float i1 = 1.f / fmaxf((float)c1, 1.f);
#pragma unroll
    for (int i = 0; i < CPL; i++) {
        int col = lane + i * 32;
        float o = g_HR[n * J + 2 * OUT + col] + rbias[col] + a0[i] * i0 + a1[i] * i1;
        xout[n * OUT + col] = tanhf(o);
    }
}

// ---------------------------------------------------------------------------
// GAT: h = x @ gat_w (32->512); asv/adv; per-node softmax; aggregate
// ---------------------------------------------------------------------------
__global__ void k_gat_h(const float* __restrict__ gw) {
    // x = g_xb (width 32), h -> g_xa (width 512). Thread computes 4 cols.
    int t = blockIdx.x * blockDim.x + threadIdx.x;
    if (t >= NN * 128) return;
    int n  = t >> 7;
    int c4 = (t & 127) << 2;
    const float* xr = g_xb + n * 32;
    float4 acc = make_float4(0.f, 0.f, 0.f, 0.f);
#pragma unroll
    for (int k = 0; k < 32; k++) {
        float xv = __ldg(xr + k);
        float4 w = *(const float4*)(gw + k * 512 + c4);
        acc.x += xv * w.x; acc.y += xv * w.y; acc.z += xv * w.z; acc.w += xv * w.w;
    }
    *(float4*)(g_xa + n * 512 + c4) = acc;
}

__global__ void k_attdot(const float* __restrict__ as, const float* __restrict__ ad) {
    int warp = (blockIdx.x * blockDim.x + threadIdx.x) >> 5;
    int lane = threadIdx.x & 31;
    if (warp >= NN) return;
    int n = warp;
    const float4* h4 = (const float4*)(g_xa + n * 512);
    const float4* a4 = (const float4*)as;
    const float4* d4 = (const float4*)ad;
    float sa = 0.f, sd = 0.f;
#pragma unroll
    for (int i = 0; i < 4; i++) {
        int idx = lane + i * 32;
        float4 hv = h4[idx];
        float4 av = a4[idx];
        float4 dv = d4[idx];
        sa += hv.x * av.x + hv.y * av.y + hv.z * av.z + hv.w * av.w;
        sd += hv.x * dv.x + hv.y * dv.y + hv.z * dv.z + hv.w * dv.w;
    }
#pragma unroll
    for (int off = 16; off; off >>= 1) {
        sa += __shfl_xor_sync(0xffffffffu, sa, off);
        sd += __shfl_xor_sync(0xffffffffu, sd, off);
    }
    if (lane == 0) { g_asv[n] = sa; g_adv[n] = sd; }
}

__global__ void k_softmax() {
    int warp = (blockIdx.x * blockDim.x + threadIdx.x) >> 5;
    int lane = threadIdx.x & 31;
    if (warp >= NN) return;
    int n = warp;
    int beg = g_rowptr[n], end = g_rowptr[n + 1];
    float advn = g_adv[n];
    float salpha = lrelu(g_asv[n] + advn);   // self loop
    float m = salpha;
    for (int e = beg + lane; e < end; e += 32) {
        float a = lrelu(g_asv[g_ssrc[e]] + advn);
        m = fmaxf(m, a);
    }
#pragma unroll
    for (int off = 16; off; off >>= 1)
        m = fmaxf(m, __shfl_xor_sync(0xffffffffu, m, off));
    float ssum = (lane == 0) ? expf(salpha - m) : 0.f;
    for (int e = beg + lane; e < end; e += 32) {
        float a = lrelu(g_asv[g_ssrc[e]] + advn);
        ssum += expf(a - m);
    }
#pragma unroll
    for (int off = 16; off; off >>= 1)
        ssum += __shfl_xor_sync(0xffffffffu, ssum, off);
    float inv = 1.f / fmaxf(ssum, 1e-16f);
    for (int e = beg + lane; e < end; e += 32) {
        float a = lrelu(g_asv[g_ssrc[e]] + advn);
        g_coef[e] = expf(a - m) * inv;
    }
    if (lane == 0) g_self[n] = expf(salpha - m) * inv;
}

// block (128 threads) per node; each thread owns 4 of 512 dims.
__global__ void k_gat_agg(const float* __restrict__ bias) {
    int n = blockIdx.x;
    int t = threadIdx.x;   // 0..127
    int beg = g_rowptr[n], end = g_rowptr[n + 1];
    float4 hv = ((const float4*)(g_xa + n * 512))[t];
    float sc = g_self[n];
    float4 acc = make_float4(sc * hv.x, sc * hv.y, sc * hv.z, sc * hv.w);
    for (int e = beg; e < end; e++) {
        float c = g_coef[e];
        int s = g_ssrc[e];
        float4 v = ((const float4*)(g_xa + s * 512))[t];
        acc.x += c * v.x; acc.y += c * v.y; acc.z += c * v.z; acc.w += c * v.w;
    }
    float4 b = ((const float4*)bias)[t];
    float4 o;
    o.x = fmaxf(acc.x + b.x, 0.f);
    o.y = fmaxf(acc.y + b.y, 0.f);
    o.z = fmaxf(acc.z + b.z, 0.f);
    o.w = fmaxf(acc.w + b.w, 0.f);
    ((float4*)(g_xb + n * 512))[t] = o;
}

// ---------------------------------------------------------------------------
// A = x @ w1[0:512, :],  B = x @ w1[512:1024, :]   (x = g_xb, [NN,512])
// Thread computes 4 contiguous columns of A or B for one row.
// ---------------------------------------------------------------------------
__global__ void k_ab(const float* __restrict__ w1) {
    int t = blockIdx.x * blockDim.x + threadIdx.x;
    if (t >= NN * 64) return;
    int n  = t >> 6;
    int cg = t & 63;
    int half = cg >> 5;               // 0 -> A, 1 -> B
    int j = (cg & 31) << 2;
    const float* wb = w1 + half * 512 * 128;
    const float* xr = g_xb + n * 512;
    float4 acc = make_float4(0.f, 0.f, 0.f, 0.f);
#pragma unroll 2
    for (int k = 0; k < 512; k += 4) {
        float4 xv = *(const float4*)(xr + k);
        float4 w0 = *(const float4*)(wb + (k + 0) * 128 + j);
        acc.x += xv.x * w0.x; acc.y += xv.x * w0.y; acc.z += xv.x * w0.z; acc.w += xv.x * w0.w;
        float4 w1v = *(const float4*)(wb + (k + 1) * 128 + j);
        acc.x += xv.y * w1v.x; acc.y += xv.y * w1v.y; acc.z += xv.y * w1v.z; acc.w += xv.y * w1v.w;
        float4 w2v = *(const float4*)(wb + (k + 2) * 128 + j);
        acc.x += xv.z * w2v.x; acc.y += xv.z * w2v.y; acc.z += xv.z * w2v.z; acc.w += xv.z * w2v.w;
        float4 w3v = *(const float4*)(wb + (k + 3) * 128 + j);
        acc.x += xv.w * w3v.x; acc.y += xv.w * w3v.y; acc.z += xv.w * w3v.z; acc.w += xv.w * w3v.w;
    }
    float* o = (half ? g_B : g_A) + n * 128 + j;
    *(float4*)o = acc;
}

// ---------------------------------------------------------------------------
// Edge MLP: h = relu(A[src] + B[dst] + b1);  out = sigmoid(h . w2 + b2)
// One warp per edge; each lane owns 4 of 128 hidden dims.
// ---------------------------------------------------------------------------
__global__ void k_mlp(const int* __restrict__ src, const int* __restrict__ dst,
                      const float* __restrict__ b1, const float* __restrict__ w2,
                      const float* __restrict__ b2, float* __restrict__ out) {
    int warp = (blockIdx.x * blockDim.x + threadIdx.x) >> 5;
    int lane = threadIdx.x & 31;
    if (warp >= EE) return;
    int e = warp;
    int s = src[e], d = dst[e];
    float4 a  = ((const float4*)(g_A + s * 128))[lane];
    float4 b  = ((const float4*)(g_B + d * 128))[lane];
    float4 bb = ((const float4*)b1)[lane];
    float4 w  = ((const float4*)w2)[lane];
    float hx = fmaxf(a.x + b.x + bb.x, 0.f);
    float hy = fmaxf(a.y + b.y + bb.y, 0.f);
    float hz = fmaxf(a.z + b.z + bb.z, 0.f);
    float hw = fmaxf(a.w + b.w + bb.w, 0.f);
    float z = hx * w.x + hy * w.y + hz * w.z + hw * w.w;
#pragma unroll
    for (int off = 16; off; off >>= 1)
        z += __shfl_xor_sync(0xffffffffu, z, off);
    if (lane == 0) {
        z += __ldg(b2);
        out[e] = 1.f / (1.f + expf(-z));
    }
}

// ---------------------------------------------------------------------------
// Launch — robust input binding:
// edge_index is the unique input with 2*EE elements; edge_type the unique one
// with EE elements. All other 24 inputs keep their relative order
// (basis0, comp0, root0, rbias0, ... basis3..rbias3, gat_w, att_src, att_dst,
//  gat_bias, w1, b1, w2, b2) under either metadata ordering convention.
// ---------------------------------------------------------------------------
extern "C" void kernel_launch(void* const* d_in, const int* in_sizes, int n_in,
                              void* d_out, int out_size) {
    int ei_idx = -1, et_idx = -1;
    for (int i = 0; i < n_in; i++) {
        if (in_sizes[i] == 2 * EE) ei_idx = i;
        else if (in_sizes[i] == EE) et_idx = i;
    }
    const float* rest[24];
    int k = 0;
    for (int i = 0; i < n_in && k < 24; i++) {
        if (i == ei_idx || i == et_idx) continue;
        rest[k++] = (const float*)d_in[i];
    }

    const int* edge_index = (const int*)d_in[ei_idx];
    const int* src = edge_index;
    const int* dst = edge_index + EE;
    const int* etype = (const int*)d_in[et_idx];

    const float* basis[4] = {rest[0], rest[4], rest[8],  rest[12]};
    const float* comp[4]  = {rest[1], rest[5], rest[9],  rest[13]};
    const float* root[4]  = {rest[2], rest[6], rest[10], rest[14]};
    const float* rbias[4] = {rest[3], rest[7], rest[11], rest[15]};
    const float* gat_w   = rest[16];
    const float* att_src = rest[17];
    const float* att_dst = rest[18];
    const float* gat_b   = rest[19];
    const float* w1 = rest[20];
    const float* b1 = rest[21];
    const float* w2 = rest[22];
    const float* b2 = rest[23];
    float* out = (float*)d_out;

    const int TB = 256;
    // CSR build
    k_zero_cnt<<<(NN + TB - 1) / TB, TB>>>();
    k_hist<<<(EE + TB - 1) / TB, TB>>>(dst);
    k_scan<<<1, 256>>>();
    k_scatter<<<(EE + TB - 1) / TB, TB>>>(src, dst, etype);

    // Layer 0 (identity input)
    k_w0<<<(2 * NN * 32 + TB - 1) / TB, TB>>>(basis[0], comp[0]);
    k_layer0<<<(NN * 32 + TB - 1) / TB, TB>>>(root[0], rbias[0]);   // -> g_xa (w=32)

    // Layer 1: in=32, out=64 : g_xa -> g_xb
    k_wcat<<<(32 * 192 + TB - 1) / TB, TB>>>(basis[1], comp[1], root[1], 32, 64);
    k_hr<<<(NN * 48 + TB - 1) / TB, TB>>>(0, 32, 64);
    k_agg<64><<<(NN * 32 + TB - 1) / TB, TB>>>(rbias[1], 1);

    // Layer 2: in=64, out=64 : g_xb -> g_xa
    k_wcat<<<(64 * 192 + TB - 1) / TB, TB>>>(basis[2], comp[2], root[2], 64, 64);
    k_hr<<<(NN * 48 + TB - 1) / TB, TB>>>(1, 64, 64);
    k_agg<64><<<(NN * 32 + TB - 1) / TB, TB>>>(rbias[2], 0);

    // Layer 3: in=64, out=32 : g_xa -> g_xb
    k_wcat<<<(64 * 96 + TB - 1) / TB, TB>>>(basis[3], comp[3], root[3], 64, 32);
    k_hr<<<(NN * 24 + TB - 1) / TB, TB>>>(0, 64, 32);
    k_agg<32><<<(NN * 32 + TB - 1) / TB, TB>>>(rbias[3], 1);

    // GAT: x = g_xb (w=32); h -> g_xa (w=512); out -> g_xb (w=512)
    k_gat_h<<<(NN * 128 + TB - 1) / TB, TB>>>(gat_w);
    k_attdot<<<(NN * 32 + TB - 1) / TB, TB>>>(att_src, att_dst);
    k_softmax<<<(NN * 32 + TB - 1) / TB, TB>>>();
    k_gat_agg<<<NN, 128>>>(gat_b);

    // Edge MLP via per-node precomputation: A = x@w1_top, B = x@w1_bot
    k_ab<<<(NN * 64 + TB - 1) / TB, TB>>>(w1);
    k_mlp<<<(EE * 32 + TB - 1) / TB, TB>>>(src, dst, b1, w2, b2, out);
}

// round 9
// speedup vs baseline: 2.3603x; 2.3603x over previous
#include <cuda_runtime.h>
#include <math.h>

// Problem constants (fixed by the reference)
#define NN 6000          // N_USERS + N_ITEMS
#define NNP 6016         // padded row count (multiple of 64) for tiled GEMM
#define EE 100000        // edges
#define NREL 2

// ---------------------------------------------------------------------------
// Device scratch (static device globals — zero-initialized, no runtime alloc)
// ---------------------------------------------------------------------------
__device__ int   g_cnt[NN];
__device__ int   g_rowptr[NN + 1];
__device__ int   g_cursor[NN];
__device__ int   g_ssrc[EE];        // CSR (by dst): source node per slot
__device__ int   g_stype[EE];       // CSR: edge type per slot

__device__ float g_W0[2 * NN * 32]; // layer-0 relation weights W[r][n][o]
__device__ float g_xa[NNP * 512];   // ping buffer (padded rows stay 0)
__device__ float g_xb[NNP * 512];   // pong buffer (padded rows stay 0)
__device__ float g_HR[NN * 192];    // per-layer [x@W0 | x@W1 | x@root]
__device__ float g_WcAll[6144 + 12288 + 6144]; // fused weights layers 1..3
__device__ float g_asv[NN];
__device__ float g_adv[NN];
__device__ float g_coef[EE];        // GAT normalized attention per CSR slot
__device__ float g_self[NN];        // GAT self-loop attention
__device__ float g_A[NNP * 128];    // x @ w1[0:512]
__device__ float g_B[NNP * 128];    // x @ w1[512:1024]

#define WC1_OFF 0
#define WC2_OFF 6144
#define WC3_OFF 18432

__device__ __forceinline__ float lrelu(float x) { return x > 0.f ? x : 0.2f * x; }

__device__ __forceinline__ float tanh_ap(float x) {
    float r;
    asm("tanh.approx.f32 %0, %1;" : "=f"(r) : "f"(x));
    return r;
}

typedef unsigned long long ull;
__device__ __forceinline__ ull pk2(float lo, float hi) {
    ull r; asm("mov.b64 %0, {%1, %2};" : "=l"(r) : "f"(lo), "f"(hi)); return r;
}
__device__ __forceinline__ void upk2(float& lo, float& hi, ull v) {
    asm("mov.b64 {%0, %1}, %2;" : "=f"(lo), "=f"(hi) : "l"(v));
}
__device__ __forceinline__ void fma2(ull& c, ull a, ull b) {
    asm("fma.rn.f32x2 %0, %1, %2, %0;" : "+l"(c) : "l"(a), "l"(b));
}

// ---------------------------------------------------------------------------
// CSR build
// ---------------------------------------------------------------------------
__global__ void k_hist(const int* __restrict__ dst) {
    int e = blockIdx.x * blockDim.x + threadIdx.x;
    if (e < EE) atomicAdd(&g_cnt[dst[e]], 1);
}

__global__ void k_scan() {
    __shared__ int sp[256];
    int tid = threadIdx.x;
    const int CH = (NN + 255) / 256;   // 24
    int base = tid * CH;
    int s = 0;
    for (int i = 0; i < CH; i++) {
        int idx = base + i;
        if (idx < NN) s += g_cnt[idx];
    }
    sp[tid] = s;
    __syncthreads();
    for (int off = 1; off < 256; off <<= 1) {
        int v = 0;
        if (tid >= off) v = sp[tid - off];
        __syncthreads();
        sp[tid] += v;
        __syncthreads();
    }
    int run = sp[tid] - s;  // exclusive prefix for this chunk
    for (int i = 0; i < CH; i++) {
        int idx = base + i;
        if (idx < NN) {
            g_rowptr[idx] = run;
            g_cursor[idx] = run;
            run += g_cnt[idx];
        }
    }
    if (tid == 255) g_rowptr[NN] = sp[255];
}

__global__ void k_scatter(const int* __restrict__ src, const int* __restrict__ dst,
                          const int* __restrict__ et) {
    int e = blockIdx.x * blockDim.x + threadIdx.x;
    if (e < EE) {
        int p = atomicAdd(&g_cursor[dst[e]], 1);
        g_ssrc[p]  = src[e];
        g_stype[p] = et[e];
    }
}

// ---------------------------------------------------------------------------
// Prep: zero g_cnt; W0 for layer 0; fused Wcat for layers 1..3.
// ---------------------------------------------------------------------------
__device__ __forceinline__ float wcat_elem(const float* __restrict__ basis,
                                           const float* __restrict__ comp,
                                           const float* __restrict__ root,
                                           int IN, int OUT, int i) {
    int J = 3 * OUT;
    int k = i / J;
    int j = i - k * J;
    if (j < 2 * OUT) {
        int r = j / OUT;
        int o = j - r * OUT;
        float v = 0.f;
#pragma unroll
        for (int b = 0; b < 4; b++)
            v += comp[r * 4 + b] * basis[(b * IN + k) * OUT + o];
        return v;
    }
    return root[k * OUT + (j - 2 * OUT)];
}

__global__ void k_prep(const float* __restrict__ basis0, const float* __restrict__ comp0,
                       const float* __restrict__ basis1, const float* __restrict__ comp1,
                       const float* __restrict__ root1,
                       const float* __restrict__ basis2, const float* __restrict__ comp2,
                       const float* __restrict__ root2,
                       const float* __restrict__ basis3, const float* __restrict__ comp3,
                       const float* __restrict__ root3) {
    int i = blockIdx.x * blockDim.x + threadIdx.x;
    if (i < 2 * NN * 32) {
        int r   = i / (NN * 32);
        int rem = i - r * (NN * 32);
        int n   = rem >> 5;
        int o   = rem & 31;
        float v = 0.f;
#pragma unroll
        for (int b = 0; b < 4; b++)
            v += comp0[r * 4 + b] * basis0[(b * NN + n) * 32 + o];
        g_W0[i] = v;
        return;
    }
    int j = i - 2 * NN * 32;
    if (j < 6144) { g_WcAll[WC1_OFF + j] = wcat_elem(basis1, comp1, root1, 32, 64, j); return; }
    j -= 6144;
    if (j < 12288) { g_WcAll[WC2_OFF + j] = wcat_elem(basis2, comp2, root2, 64, 64, j); return; }
    j -= 12288;
    if (j < 6144) { g_WcAll[WC3_OFF + j] = wcat_elem(basis3, comp3, root3, 64, 32, j); return; }
    j -= 6144;
    if (j < NN) g_cnt[j] = 0;
}

// ---------------------------------------------------------------------------
// Layer 0 (x = I): out[n] = tanh(root0[n]+rbias0 + sum_r mean W0[r][src])
// ---------------------------------------------------------------------------
__global__ void k_layer0(const float* __restrict__ root0, const float* __restrict__ rbias0) {
    int warp = (blockIdx.x * blockDim.x + threadIdx.x) >> 5;
    int lane = threadIdx.x & 31;
    if (warp >= NN) return;
    int n = warp;
    int beg = g_rowptr[n], end = g_rowptr[n + 1];
    float a0 = 0.f, a1 = 0.f;
    int c0 = 0, c1 = 0;
    for (int e = beg; e < end; e++) {
        int s = g_ssrc[e];
        int t = g_stype[e];
        float v = g_W0[(t * NN + s) * 32 + lane];
        if (t == 0) { a0 += v; c0++; } else { a1 += v; c1++; }
    }
    float o = root0[n * 32 + lane] + rbias0[lane]
            + a0 / fmaxf((float)c0, 1.f) + a1 / fmaxf((float)c1, 1.f);
    g_xa[n * 32 + lane] = tanh_ap(o);
}

// ---------------------------------------------------------------------------
// Layers 1..3: HR = x @ Wcat ([in, 3*out]); 4-row register blocking.
// ---------------------------------------------------------------------------
template <int IN, int OUT>
__global__ void k_hr(int xsel, int wcoff) {
    const float* x = xsel ? g_xb : g_xa;
    const float* W = g_WcAll + wcoff;
    const int J = 3 * OUT;
    const int cpr = J >> 2;
    int t = blockIdx.x * blockDim.x + threadIdx.x;
    if (t >= (NN / 4) * cpr) return;
    int nb = t / cpr;
    int c4 = (t - nb * cpr) << 2;
    int n0 = nb * 4;
    float4 acc[4];
#pragma unroll
    for (int r = 0; r < 4; r++) acc[r] = make_float4(0.f, 0.f, 0.f, 0.f);
#pragma unroll 4
    for (int k = 0; k < IN; k++) {
        float4 w = *(const float4*)(W + k * J + c4);
#pragma unroll
        for (int r = 0; r < 4; r++) {
            float xv = __ldg(x + (n0 + r) * IN + k);
            acc[r].x += xv * w.x; acc[r].y += xv * w.y;
            acc[r].z += xv * w.z; acc[r].w += xv * w.w;
        }
    }
#pragma unroll
    for (int r = 0; r < 4; r++)
        *(float4*)(g_HR + (n0 + r) * J + c4) = acc[r];
}

template <int OUT>
__global__ void k_agg(const float* __restrict__ rbias, int osel) {
    float* xout = osel ? g_xb : g_xa;
    const int J = 3 * OUT;
    const int CPL = OUT / 32;
    int warp = (blockIdx.x * blockDim.x + threadIdx.x) >> 5;
    int lane = threadIdx.x & 31;
    if (warp >= NN) return;
    int n = warp;
    int beg = g_rowptr[n], end = g_rowptr[n + 1];
    float a0[CPL], a1[CPL];
#pragma unroll
    for (int i = 0; i < CPL; i++) { a0[i] = 0.f; a1[i] = 0.f; }
    int c0 = 0, c1 = 0;
    for (int e = beg; e < end; e++) {
        int s = g_ssrc[e];
        int t = g_stype[e];
        const float* hrow = g_HR + s * J + t * OUT;
        if (t == 0) {
            c0++;
#pragma unroll
            for (int i = 0; i < CPL; i++) a0[i] += hrow[lane + i * 32];
        } else {
            c1++;
#pragma unroll
            for (int i = 0; i < CPL; i++) a1[i] += hrow[lane + i * 32];
        }
    }
    float i0 = 1.f / fmaxf((float)c0, 1.f);
    float i1 = 1.f / fmaxf((float)c1, 1.f);
#pragma unroll
    for (int i = 0; i < CPL; i++) {
        int col = lane + i * 32;
        float o = g_HR[n * J + 2 * OUT + col] + rbias[col] + a0[i] * i0 + a1[i] * i1;
        xout[n * OUT + col] = tanh_ap(o);
    }
}

// ---------------------------------------------------------------------------
// GAT: h = x @ gat_w (32->512); 4-row register blocking.
// x = g_xb (w=32), h -> g_xa (w=512)
// ---------------------------------------------------------------------------
__global__ void k_gat_h(const float* __restrict__ gw) {
    int t = blockIdx.x * blockDim.x + threadIdx.x;
    if (t >= (NN / 4) * 128) return;
    int nb = t >> 7;                 // 0..1499
    int c4 = (t & 127) << 2;
    int n0 = nb * 4;
    float4 acc[4];
#pragma unroll
    for (int r = 0; r < 4; r++) acc[r] = make_float4(0.f, 0.f, 0.f, 0.f);
#pragma unroll 4
    for (int k = 0; k < 32; k++) {
        float4 w = *(const float4*)(gw + k * 512 + c4);
#pragma unroll
        for (int r = 0; r < 4; r++) {
            float xv = __ldg(g_xb + (n0 + r) * 32 + k);
            acc[r].x += xv * w.x; acc[r].y += xv * w.y;
            acc[r].z += xv * w.z; acc[r].w += xv * w.w;
        }
    }
#pragma unroll
    for (int r = 0; r < 4; r++)
        *(float4*)(g_xa + (n0 + r) * 512 + c4) = acc[r];
}

__global__ void k_attdot(const float* __restrict__ as, const float* __restrict__ ad) {
    int warp = (blockIdx.x * blockDim.x + threadIdx.x) >> 5;
    int lane = threadIdx.x & 31;
    if (warp >= NN) return;
    int n = warp;
    const float4* h4 = (const float4*)(g_xa + n * 512);
    const float4* a4 = (const float4*)as;
    const float4* d4 = (const float4*)ad;
    float sa = 0.f, sd = 0.f;
#pragma unroll
    for (int i = 0; i < 4; i++) {
        int idx = lane + i * 32;
        float4 hv = h4[idx];
        float4 av = a4[idx];
        float4 dv = d4[idx];
        sa += hv.x * av.x + hv.y * av.y + hv.z * av.z + hv.w * av.w;
        sd += hv.x * dv.x + hv.y * dv.y + hv.z * dv.z + hv.w * dv.w;
    }
#pragma unroll
    for (int off = 16; off; off >>= 1) {
        sa += __shfl_xor_sync(0xffffffffu, sa, off);
        sd += __shfl_xor_sync(0xffffffffu, sd, off);
    }
    if (lane == 0) { g_asv[n] = sa; g_adv[n] = sd; }
}

__global__ void k_softmax() {
    int warp = (blockIdx.x * blockDim.x + threadIdx.x) >> 5;
    int lane = threadIdx.x & 31;
    if (warp >= NN) return;
    int n = warp;
    int beg = g_rowptr[n], end = g_rowptr[n + 1];
    float advn = g_adv[n];
    float salpha = lrelu(g_asv[n] + advn);   // self loop
    float m = salpha;
    for (int e = beg + lane; e < end; e += 32) {
        float a = lrelu(g_asv[g_ssrc[e]] + advn);
        m = fmaxf(m, a);
    }
#pragma unroll
    for (int off = 16; off; off >>= 1)
        m = fmaxf(m, __shfl_xor_sync(0xffffffffu, m, off));
    float ssum = (lane == 0) ? __expf(salpha - m) : 0.f;
    for (int e = beg + lane; e < end; e += 32) {
        float a = lrelu(g_asv[g_ssrc[e]] + advn);
        ssum += __expf(a - m);
    }
#pragma unroll
    for (int off = 16; off; off >>= 1)
        ssum += __shfl_xor_sync(0xffffffffu, ssum, off);
    float inv = 1.f / fmaxf(ssum, 1e-16f);
    for (int e = beg + lane; e < end; e += 32) {
        float a = lrelu(g_asv[g_ssrc[e]] + advn);
        g_coef[e] = __expf(a - m) * inv;
    }
    if (lane == 0) g_self[n] = __expf(salpha - m) * inv;
}

// block (128 threads) per node; each thread owns 4 of 512 dims.
__global__ void k_gat_agg(const float* __restrict__ bias) {
    int n = blockIdx.x;
    int t = threadIdx.x;   // 0..127
    int beg = g_rowptr[n], end = g_rowptr[n + 1];
    float4 hv = ((const float4*)(g_xa + n * 512))[t];
    float sc = g_self[n];
    float4 acc = make_float4(sc * hv.x, sc * hv.y, sc * hv.z, sc * hv.w);
    for (int e = beg; e < end; e++) {
        float c = g_coef[e];
        int s = g_ssrc[e];
        float4 v = ((const float4*)(g_xa + s * 512))[t];
        acc.x += c * v.x; acc.y += c * v.y; acc.z += c * v.z; acc.w += c * v.w;
    }
    float4 b = ((const float4*)bias)[t];
    float4 o;
    o.x = fmaxf(acc.x + b.x, 0.f);
    o.y = fmaxf(acc.y + b.y, 0.f);
    o.z = fmaxf(acc.z + b.z, 0.f);
    o.w = fmaxf(acc.w + b.w, 0.f);
    ((float4*)(g_xb + n * 512))[t] = o;
}

// ---------------------------------------------------------------------------
// A = x @ w1[0:512,:], B = x @ w1[512:,:]  — smem-tiled GEMM + packed f32x2.
// grid (NNP/64, 2), 256 threads. BM=64, BN=128, BK=32, per-thread 8x4.
// Padded x rows (6000..6015) are zero -> harmless outputs into padded A/B.
// ---------------------------------------------------------------------------
__global__ __launch_bounds__(256) void k_ab(const float* __restrict__ w1) {
    __shared__ float xs[32][64];    // [k][m]
    __shared__ float ws[32][128];   // [k][n]
    int m0 = blockIdx.x * 64;
    const float* wb = w1 + blockIdx.y * (512 * 128);
    int tid = threadIdx.x;
    int col = (tid & 31) * 4;       // 0..124
    int row = (tid >> 5) * 8;       // 0..56
    ull accp[4][4];                 // [row-pair][col], each packs rows (2r2, 2r2+1)
#pragma unroll
    for (int i = 0; i < 4; i++)
#pragma unroll
        for (int j = 0; j < 4; j++) accp[i][j] = pk2(0.f, 0.f);

    for (int k0 = 0; k0 < 512; k0 += 32) {
        // x tile: 64 rows x 32 k  (512 float4, 2 per thread)
#pragma unroll
        for (int i = 0; i < 2; i++) {
            int idx = tid + i * 256;
            int m = idx >> 3;
            int k4 = (idx & 7) * 4;
            float4 v = *(const float4*)(g_xb + (m0 + m) * 512 + k0 + k4);
            xs[k4 + 0][m] = v.x; xs[k4 + 1][m] = v.y;
            xs[k4 + 2][m] = v.z; xs[k4 + 3][m] = v.w;
        }
        // w tile: 32 k x 128 cols (1024 float4, 4 per thread)
#pragma unroll
        for (int i = 0; i < 4; i++) {
            int idx = tid + i * 256;
            int kk = idx >> 5;
            int c4 = (idx & 31) * 4;
            *(float4*)&ws[kk][c4] = *(const float4*)(wb + (k0 + kk) * 128 + c4);
        }
        __syncthreads();
#pragma unroll
        for (int kk = 0; kk < 32; kk++) {
            float4 w = *(const float4*)&ws[kk][col];
            ull wd0 = pk2(w.x, w.x), wd1 = pk2(w.y, w.y);
            ull wd2 = pk2(w.z, w.z), wd3 = pk2(w.w, w.w);
#pragma unroll
            for (int r2 = 0; r2 < 4; r2++) {
                ull xp = *(const ull*)&xs[kk][row + 2 * r2];  // rows (2r2, 2r2+1)
                fma2(accp[r2][0], xp, wd0);
                fma2(accp[r2][1], xp, wd1);
                fma2(accp[r2][2], xp, wd2);
                fma2(accp[r2][3], xp, wd3);
            }
        }
        __syncthreads();
    }
    float* ob = blockIdx.y ? g_B : g_A;
#pragma unroll
    for (int r2 = 0; r2 < 4; r2++) {
        float4 vlo, vhi;
        upk2(vlo.x, vhi.x, accp[r2][0]);
        upk2(vlo.y, vhi.y, accp[r2][1]);
        upk2(vlo.z, vhi.z, accp[r2][2]);
        upk2(vlo.w, vhi.w, accp[r2][3]);
        *(float4*)(ob + (m0 + row + 2 * r2 + 0) * 128 + col) = vlo;
        *(float4*)(ob + (m0 + row + 2 * r2 + 1) * 128 + col) = vhi;
    }
}

// ---------------------------------------------------------------------------
// Edge MLP: h = relu(A[src] + B[dst] + b1);  out = sigmoid(h . w2 + b2)
// One warp per edge; each lane owns 4 of 128 hidden dims.
// ---------------------------------------------------------------------------
__global__ void k_mlp(const int* __restrict__ src, const int* __restrict__ dst,
                      const float* __restrict__ b1, const float* __restrict__ w2,
                      const float* __restrict__ b2, float* __restrict__ out) {
    int warp = (blockIdx.x * blockDim.x + threadIdx.x) >> 5;
    int lane = threadIdx.x & 31;
    if (warp >= EE) return;
    int e = warp;
    int s = src[e], d = dst[e];
    float4 a  = ((const float4*)(g_A + s * 128))[lane];
    float4 b  = ((const float4*)(g_B + d * 128))[lane];
    float4 bb = ((const float4*)b1)[lane];
    float4 w  = ((const float4*)w2)[lane];
    float hx = fmaxf(a.x + b.x + bb.x, 0.f);
    float hy = fmaxf(a.y + b.y + bb.y, 0.f);
    float hz = fmaxf(a.z + b.z + bb.z, 0.f);
    float hw = fmaxf(a.w + b.w + bb.w, 0.f);
    float z = hx * w.x + hy * w.y + hz * w.z + hw * w.w;
#pragma unroll
    for (int off = 16; off; off >>= 1)
        z += __shfl_xor_sync(0xffffffffu, z, off);
    if (lane == 0) {
        z += __ldg(b2);
        out[e] = 1.f / (1.f + __expf(-z));
    }
}

// ---------------------------------------------------------------------------
// Launch — robust input binding by element count (edge_index: 2*EE ints,
// edge_type: EE ints; remaining 24 float inputs keep relative order).
// ---------------------------------------------------------------------------
extern "C" void kernel_launch(void* const* d_in, const int* in_sizes, int n_in,
                              void* d_out, int out_size) {
    int ei_idx = -1, et_idx = -1;
    for (int i = 0; i < n_in; i++) {
        if (in_sizes[i] == 2 * EE) ei_idx = i;
        else if (in_sizes[i] == EE) et_idx = i;
    }
    const float* rest[24];
    int k = 0;
    for (int i = 0; i < n_in && k < 24; i++) {
        if (i == ei_idx || i == et_idx) continue;
        rest[k++] = (const float*)d_in[i];
    }

    const int* edge_index = (const int*)d_in[ei_idx];
    const int* src = edge_index;
    const int* dst = edge_index + EE;
    const int* etype = (const int*)d_in[et_idx];

    const float* basis[4] = {rest[0], rest[4], rest[8],  rest[12]};
    const float* comp[4]  = {rest[1], rest[5], rest[9],  rest[13]};
    const float* root[4]  = {rest[2], rest[6], rest[10], rest[14]};
    const float* rbias[4] = {rest[3], rest[7], rest[11], rest[15]};
    const float* gat_w   = rest[16];
    const float* att_src = rest[17];
    const float* att_dst = rest[18];
    const float* gat_b   = rest[19];
    const float* w1 = rest[20];
    const float* b1 = rest[21];
    const float* w2 = rest[22];
    const float* b2 = rest[23];
    float* out = (float*)d_out;

    const int TB = 256;
    // Prep (W0 + Wcat1..3 + zero g_cnt) and CSR build
    const int PREP = 2 * NN * 32 + 6144 + 12288 + 6144 + NN;
    k_prep<<<(PREP + TB - 1) / TB, TB>>>(basis[0], comp[0],
                                         basis[1], comp[1], root[1],
                                         basis[2], comp[2], root[2],
                                         basis[3], comp[3], root[3]);
    k_hist<<<(EE + TB - 1) / TB, TB>>>(dst);
    k_scan<<<1, 256>>>();
    k_scatter<<<(EE + TB - 1) / TB, TB>>>(src, dst, etype);

    // Layer 0 (identity input) -> g_xa (w=32)
    k_layer0<<<(NN * 32 + TB - 1) / TB, TB>>>(root[0], rbias[0]);

    // Layer 1: in=32, out=64 : g_xa -> g_xb
    k_hr<32, 64><<<((NN / 4) * 48 + TB - 1) / TB, TB>>>(0, WC1_OFF);
    k_agg<64><<<(NN * 32 + TB - 1) / TB, TB>>>(rbias[1], 1);

    // Layer 2: in=64, out=64 : g_xb -> g_xa
    k_hr<64, 64><<<((NN / 4) * 48 + TB - 1) / TB, TB>>>(1, WC2_OFF);
    k_agg<64><<<(NN * 32 + TB - 1) / TB, TB>>>(rbias[2], 0);

    // Layer 3: in=64, out=32 : g_xa -> g_xb
    k_hr<64, 32><<<((NN / 4) * 24 + TB - 1) / TB, TB>>>(0, WC3_OFF);
    k_agg<32><<<(NN * 32 + TB - 1) / TB, TB>>>(rbias[3], 1);

    // GAT: x = g_xb (w=32); h -> g_xa (w=512); out -> g_xb (w=512)
    k_gat_h<<<((NN / 4) * 128 + TB - 1) / TB, TB>>>(gat_w);
    k_attdot<<<(NN * 32 + TB - 1) / TB, TB>>>(att_src, att_dst);
    k_softmax<<<(NN * 32 + TB - 1) / TB, TB>>>();
    k_gat_agg<<<NN, 128>>>(gat_b);

    // Edge MLP via per-node precomputation: A = x@w1_top, B = x@w1_bot
    dim3 gab(NNP / 64, 2);
    k_ab<<<gab, 256>>>(w1);
    k_mlp<<<(EE * 32 + TB - 1) / TB, TB>>>(src, dst, b1, w2, b2, out);
}